// round 3
// baseline (speedup 1.0000x reference)
#include <cuda_runtime.h>

#define NHEAD 32
#define DK    8
#define EDIM  256
#define MAXTOK (16 * 4096)

// 64 MB scratch for the attention output (pre-projection). Static __device__
// array: no allocation, graph-capture safe.
__device__ float g_mid[(size_t)MAXTOK * EDIM];

// ---------------------------------------------------------------------------
// Kernel 1: per-token quantum attention.
// One warp per token. lane = head index h.
//   q[h][d] = cos(x[tok, h*8+d] + theta[d])
//   s[h][g] = (q[h].q[g]) / sqrt(8) ; softmax over g ; out[h] = sum_g a[g] q[g]
// ---------------------------------------------------------------------------
__global__ void __launch_bounds__(128) attn_kernel(
    const float* __restrict__ x,
    const float* __restrict__ theta,
    int ntok)
{
    __shared__ __align__(16) float qs[4][NHEAD][DK];   // 4 warps/block, 4 KB
    const int wl   = threadIdx.x >> 5;
    const int lane = threadIdx.x & 31;
    const int tok  = (blockIdx.x << 2) + wl;
    if (tok >= ntok) return;

    const float4* xp = reinterpret_cast<const float4*>(x + (size_t)tok * EDIM + lane * DK);
    const float4 x0 = xp[0];
    const float4 x1 = xp[1];
    const float4 t0 = *reinterpret_cast<const float4*>(theta);
    const float4 t1 = *reinterpret_cast<const float4*>(theta + 4);

    float q[8];
    q[0] = __cosf(x0.x + t0.x);
    q[1] = __cosf(x0.y + t0.y);
    q[2] = __cosf(x0.z + t0.z);
    q[3] = __cosf(x0.w + t0.w);
    q[4] = __cosf(x1.x + t1.x);
    q[5] = __cosf(x1.y + t1.y);
    q[6] = __cosf(x1.z + t1.z);
    q[7] = __cosf(x1.w + t1.w);

    float4* qrow = reinterpret_cast<float4*>(&qs[wl][lane][0]);
    qrow[0] = make_float4(q[0], q[1], q[2], q[3]);
    qrow[1] = make_float4(q[4], q[5], q[6], q[7]);
    __syncwarp();

    // Gram row h (this lane's row), over all g. Broadcast shared reads.
    float s[NHEAD];
#pragma unroll
    for (int g = 0; g < NHEAD; ++g) {
        const float4 a = *reinterpret_cast<const float4*>(&qs[wl][g][0]);
        const float4 b = *reinterpret_cast<const float4*>(&qs[wl][g][4]);
        float d = q[0] * a.x + q[1] * a.y + q[2] * a.z + q[3] * a.w
                + q[4] * b.x + q[5] * b.y + q[6] * b.z + q[7] * b.w;
        s[g] = d * 0.35355339059327373f;   // 1/sqrt(8)
    }

    float m = s[0];
#pragma unroll
    for (int g = 1; g < NHEAD; ++g) m = fmaxf(m, s[g]);

    float ssum = 0.f;
#pragma unroll
    for (int g = 0; g < NHEAD; ++g) {
        s[g] = __expf(s[g] - m);
        ssum += s[g];
    }
    const float inv = 1.0f / ssum;

    float acc0 = 0.f, acc1 = 0.f, acc2 = 0.f, acc3 = 0.f;
    float acc4 = 0.f, acc5 = 0.f, acc6 = 0.f, acc7 = 0.f;
#pragma unroll
    for (int g = 0; g < NHEAD; ++g) {
        const float4 a = *reinterpret_cast<const float4*>(&qs[wl][g][0]);
        const float4 b = *reinterpret_cast<const float4*>(&qs[wl][g][4]);
        const float w = s[g];
        acc0 += w * a.x; acc1 += w * a.y; acc2 += w * a.z; acc3 += w * a.w;
        acc4 += w * b.x; acc5 += w * b.y; acc6 += w * b.z; acc7 += w * b.w;
    }

    float4* op = reinterpret_cast<float4*>(g_mid + (size_t)tok * EDIM + lane * DK);
    op[0] = make_float4(acc0 * inv, acc1 * inv, acc2 * inv, acc3 * inv);
    op[1] = make_float4(acc4 * inv, acc5 * inv, acc6 * inv, acc7 * inv);
}

// ---------------------------------------------------------------------------
// Kernel 2: C[M, 256] = g_mid[M, 256] @ W^T[256, 256] + bias
// Classic fp32 SGEMM: 128x128 block tile, BK=8, 256 threads, 8x8 micro-tile.
// Both operands K-contiguous (TN). No Blackwell-Ultra-only instructions.
// Fragments are split 4+4 (cols tx*4 and 64+tx*4) so mainloop LDS.128 lanes
// stride 16B -> conflict-free.
// ---------------------------------------------------------------------------
#define BM 128
#define BN 128
#define BK 8
#define LDSPAD 132   // row length in floats (528 B: 16B-aligned, conflict-free stores)

__global__ void __launch_bounds__(256) gemm_kernel(
    const float* __restrict__ W,
    const float* __restrict__ bias,
    float* __restrict__ C, int M)
{
    __shared__ __align__(16) float As[BK][LDSPAD];
    __shared__ __align__(16) float Bs[BK][LDSPAD];

    const int tid = threadIdx.x;
    const int tx  = tid & 15;        // N micro index
    const int ty  = tid >> 4;        // M micro index
    const int m0  = blockIdx.x * BM;
    const int n0  = blockIdx.y * BN;

    // Load mapping: each thread loads one float4 along K for A and B.
    const int lrow = tid >> 1;          // 0..127
    const int lk   = (tid & 1) * 4;     // 0 or 4

    const float* aSrc = g_mid + (size_t)(m0 + lrow) * EDIM + lk;
    const float* bSrc = W + (size_t)(n0 + lrow) * EDIM + lk;
    const bool aValid = (m0 + lrow) < M;

    float acc[8][8];
#pragma unroll
    for (int i = 0; i < 8; ++i)
#pragma unroll
        for (int j = 0; j < 8; ++j) acc[i][j] = 0.f;

    // Prologue: load first tiles.
    float4 aReg = aValid ? *reinterpret_cast<const float4*>(aSrc)
                         : make_float4(0.f, 0.f, 0.f, 0.f);
    float4 bReg = *reinterpret_cast<const float4*>(bSrc);

    for (int kc = 0; kc < EDIM; kc += BK) {
        // Commit prefetched tile to smem (transposed: As[k][m]).
        As[lk + 0][lrow] = aReg.x;
        As[lk + 1][lrow] = aReg.y;
        As[lk + 2][lrow] = aReg.z;
        As[lk + 3][lrow] = aReg.w;
        Bs[lk + 0][lrow] = bReg.x;
        Bs[lk + 1][lrow] = bReg.y;
        Bs[lk + 2][lrow] = bReg.z;
        Bs[lk + 3][lrow] = bReg.w;
        __syncthreads();

        // Prefetch next tile while computing on this one.
        if (kc + BK < EDIM) {
            aReg = aValid ? *reinterpret_cast<const float4*>(aSrc + kc + BK)
                          : make_float4(0.f, 0.f, 0.f, 0.f);
            bReg = *reinterpret_cast<const float4*>(bSrc + kc + BK);
        }

#pragma unroll
        for (int k = 0; k < BK; ++k) {
            const float4 a0 = *reinterpret_cast<const float4*>(&As[k][ty * 4]);
            const float4 a1 = *reinterpret_cast<const float4*>(&As[k][64 + ty * 4]);
            const float4 b0 = *reinterpret_cast<const float4*>(&Bs[k][tx * 4]);
            const float4 b1 = *reinterpret_cast<const float4*>(&Bs[k][64 + tx * 4]);
            const float av[8] = {a0.x, a0.y, a0.z, a0.w, a1.x, a1.y, a1.z, a1.w};
            const float bv[8] = {b0.x, b0.y, b0.z, b0.w, b1.x, b1.y, b1.z, b1.w};
#pragma unroll
            for (int i = 0; i < 8; ++i)
#pragma unroll
                for (int j = 0; j < 8; ++j)
                    acc[i][j] = fmaf(av[i], bv[j], acc[i][j]);
        }
        __syncthreads();
    }

    // Epilogue: add bias, store.
    const float4 bl = *reinterpret_cast<const float4*>(&bias[n0 + tx * 4]);
    const float4 bh = *reinterpret_cast<const float4*>(&bias[n0 + 64 + tx * 4]);

#pragma unroll
    for (int i = 0; i < 8; ++i) {
        const int row = m0 + ((i < 4) ? (ty * 4 + i) : (64 + ty * 4 + (i - 4)));
        if (row >= M) continue;
        *reinterpret_cast<float4*>(&C[(size_t)row * EDIM + n0 + tx * 4]) =
            make_float4(acc[i][0] + bl.x, acc[i][1] + bl.y,
                        acc[i][2] + bl.z, acc[i][3] + bl.w);
        *reinterpret_cast<float4*>(&C[(size_t)row * EDIM + n0 + 64 + tx * 4]) =
            make_float4(acc[i][4] + bh.x, acc[i][5] + bh.y,
                        acc[i][6] + bh.z, acc[i][7] + bh.w);
    }
}

// ---------------------------------------------------------------------------
extern "C" void kernel_launch(void* const* d_in, const int* in_sizes, int n_in,
                              void* d_out, int out_size)
{
    const float* x     = (const float*)d_in[0];
    const float* theta = (const float*)d_in[1];
    const float* W     = (const float*)d_in[2];
    const float* bias  = (const float*)d_in[3];
    float* out = (float*)d_out;

    int ntok = in_sizes[0] / EDIM;
    if (ntok > MAXTOK) ntok = MAXTOK;

    attn_kernel<<<(ntok + 3) / 4, 128>>>(x, theta, ntok);

    dim3 grid((ntok + BM - 1) / BM, EDIM / BN);
    gemm_kernel<<<grid, 256>>>(W, bias, out, ntok);
}

// round 8
// speedup vs baseline: 1.8407x; 1.8407x over previous
#include <cuda_runtime.h>
#include <cuda_bf16.h>

#define NHEAD 32
#define DK    8
#define EDIM  256
#define MAXTOK (16 * 4096)

// Scratch (static __device__: no allocation, graph-capture safe).
// Attention output and W, each split into bf16 hi + bf16 lo (residual).
__device__ __nv_bfloat16 g_midh[(size_t)MAXTOK * EDIM];
__device__ __nv_bfloat16 g_midl[(size_t)MAXTOK * EDIM];
__device__ __nv_bfloat16 g_Wh[EDIM * EDIM];
__device__ __nv_bfloat16 g_Wl[EDIM * EDIM];

__device__ __forceinline__ unsigned pack2(float a, float b) {
    __nv_bfloat162 t = __floats2bfloat162_rn(a, b);
    return *reinterpret_cast<unsigned*>(&t);
}
__device__ __forceinline__ float bf16_residual(float v) {
    return v - __bfloat162float(__float2bfloat16_rn(v));
}

// ---------------------------------------------------------------------------
// Kernel 0: W (fp32) -> g_Wh + g_Wl (bf16 split). 65536 elems, 8 per thread.
// ---------------------------------------------------------------------------
__global__ void __launch_bounds__(256) wconv_kernel(const float* __restrict__ W)
{
    const int i = (blockIdx.x * 256 + threadIdx.x) * 8;
    float v[8];
    *reinterpret_cast<float4*>(v)     = *reinterpret_cast<const float4*>(W + i);
    *reinterpret_cast<float4*>(v + 4) = *reinterpret_cast<const float4*>(W + i + 4);
    uint4 h, l;
    h.x = pack2(v[0], v[1]); h.y = pack2(v[2], v[3]);
    h.z = pack2(v[4], v[5]); h.w = pack2(v[6], v[7]);
    l.x = pack2(bf16_residual(v[0]), bf16_residual(v[1]));
    l.y = pack2(bf16_residual(v[2]), bf16_residual(v[3]));
    l.z = pack2(bf16_residual(v[4]), bf16_residual(v[5]));
    l.w = pack2(bf16_residual(v[6]), bf16_residual(v[7]));
    *reinterpret_cast<uint4*>(g_Wh + i) = h;
    *reinterpret_cast<uint4*>(g_Wl + i) = l;
}

// ---------------------------------------------------------------------------
// Kernel 1: per-token quantum attention. One warp per token, lane = head.
//   q[h][d] = cos(x[tok,h*8+d] + theta[d])
//   w[g] = exp(q[h].q[g]/sqrt(8))   (scores bounded by 2.83 -> no max pass)
//   out[h] -> bf16 hi/lo split into g_midh / g_midl
// ---------------------------------------------------------------------------
__global__ void __launch_bounds__(128) attn_kernel(
    const float* __restrict__ x,
    const float* __restrict__ theta,
    int ntok)
{
    __shared__ __align__(16) float qs[4][NHEAD][DK];   // 4 warps/block, 4 KB
    const int wl   = threadIdx.x >> 5;
    const int lane = threadIdx.x & 31;
    const int tok  = (blockIdx.x << 2) + wl;
    if (tok >= ntok) return;

    const float4* xp = reinterpret_cast<const float4*>(x + (size_t)tok * EDIM + lane * DK);
    const float4 x0 = xp[0];
    const float4 x1 = xp[1];
    const float4 t0 = *reinterpret_cast<const float4*>(theta);
    const float4 t1 = *reinterpret_cast<const float4*>(theta + 4);

    float q[8];
    q[0] = __cosf(x0.x + t0.x);
    q[1] = __cosf(x0.y + t0.y);
    q[2] = __cosf(x0.z + t0.z);
    q[3] = __cosf(x0.w + t0.w);
    q[4] = __cosf(x1.x + t1.x);
    q[5] = __cosf(x1.y + t1.y);
    q[6] = __cosf(x1.z + t1.z);
    q[7] = __cosf(x1.w + t1.w);

    float4* qrow = reinterpret_cast<float4*>(&qs[wl][lane][0]);
    qrow[0] = make_float4(q[0], q[1], q[2], q[3]);
    qrow[1] = make_float4(q[4], q[5], q[6], q[7]);
    __syncwarp();

    // Pass 1: Gram row + exp fused. Broadcast shared reads (conflict-free).
    float w[NHEAD];
#pragma unroll
    for (int g = 0; g < NHEAD; ++g) {
        const float4 a = *reinterpret_cast<const float4*>(&qs[wl][g][0]);
        const float4 b = *reinterpret_cast<const float4*>(&qs[wl][g][4]);
        float d = q[0] * a.x + q[1] * a.y + q[2] * a.z + q[3] * a.w
                + q[4] * b.x + q[5] * b.y + q[6] * b.z + q[7] * b.w;
        w[g] = __expf(d * 0.35355339059327373f);   // |arg| <= 2.83: safe
    }

    // Pass 2: weighted sum + normalizer fused.
    float ssum = 0.f;
    float acc[8] = {0.f, 0.f, 0.f, 0.f, 0.f, 0.f, 0.f, 0.f};
#pragma unroll
    for (int g = 0; g < NHEAD; ++g) {
        const float4 a = *reinterpret_cast<const float4*>(&qs[wl][g][0]);
        const float4 b = *reinterpret_cast<const float4*>(&qs[wl][g][4]);
        const float wg = w[g];
        ssum += wg;
        acc[0] += wg * a.x; acc[1] += wg * a.y; acc[2] += wg * a.z; acc[3] += wg * a.w;
        acc[4] += wg * b.x; acc[5] += wg * b.y; acc[6] += wg * b.z; acc[7] += wg * b.w;
    }
    const float inv = 1.0f / ssum;
#pragma unroll
    for (int i = 0; i < 8; ++i) acc[i] *= inv;

    uint4 h, l;
    h.x = pack2(acc[0], acc[1]); h.y = pack2(acc[2], acc[3]);
    h.z = pack2(acc[4], acc[5]); h.w = pack2(acc[6], acc[7]);
    l.x = pack2(bf16_residual(acc[0]), bf16_residual(acc[1]));
    l.y = pack2(bf16_residual(acc[2]), bf16_residual(acc[3]));
    l.z = pack2(bf16_residual(acc[4]), bf16_residual(acc[5]));
    l.w = pack2(bf16_residual(acc[6]), bf16_residual(acc[7]));
    *reinterpret_cast<uint4*>(g_midh + (size_t)tok * EDIM + lane * DK) = h;
    *reinterpret_cast<uint4*>(g_midl + (size_t)tok * EDIM + lane * DK) = l;
}

// ---------------------------------------------------------------------------
// Kernel 2: C = (Ah+Al) @ (Wh+Wl)^T + bias  ~=  Ah Wh^T + Ah Wl^T + Al Wh^T
// via bf16 mma.sync.m16n8k16 (the path proven to execute in round 4).
// 3 segments x 8 k-steps over the same 128x128 block structure.
// ---------------------------------------------------------------------------
#define GBM 128
#define GBN 128
#define GBK 32
#define KSTR 40
#define NSEG 3
#define NKC  (EDIM / GBK)          // 8
#define NIT  (NSEG * NKC)          // 24

__device__ __forceinline__ void mma16816(float* d, const unsigned* a, const unsigned* b) {
    asm volatile(
        "mma.sync.aligned.m16n8k16.row.col.f32.bf16.bf16.f32 "
        "{%0,%1,%2,%3}, {%4,%5,%6,%7}, {%8,%9}, {%0,%1,%2,%3};\n"
        : "+f"(d[0]), "+f"(d[1]), "+f"(d[2]), "+f"(d[3])
        : "r"(a[0]), "r"(a[1]), "r"(a[2]), "r"(a[3]), "r"(b[0]), "r"(b[1]));
}

__global__ void __launch_bounds__(256) gemm_bf16s_kernel(
    const float* __restrict__ bias,
    float* __restrict__ C, int M)
{
    __shared__ __align__(16) __nv_bfloat16 As[GBM][KSTR];
    __shared__ __align__(16) __nv_bfloat16 Bs[GBN][KSTR];

    const int t    = threadIdx.x;
    const int warp = t >> 5;
    const int lane = t & 31;
    const int wm   = warp >> 2;      // 0..1  (M)
    const int wn   = warp & 3;       // 0..3  (N)
    const int gid  = lane >> 2;      // 0..7
    const int tig  = lane & 3;       // 0..3
    const int m0   = blockIdx.x * GBM;
    const int n0   = blockIdx.y * GBN;

    // gmem->smem mapping: each thread 2x16B for A and 2x16B for B.
    const int lr = t >> 2;           // 0..63 (rows; +64 second pass)
    const int lc = (t & 3) * 8;      // k offset (8 bf16 = 16B chunks)

    // Segment operand tables: Ah*Bh, Ah*Bl, Al*Bh.
    const __nv_bfloat16* aSeg[NSEG] = {
        g_midh + (size_t)m0 * EDIM, g_midh + (size_t)m0 * EDIM, g_midl + (size_t)m0 * EDIM };
    const __nv_bfloat16* bSeg[NSEG] = {
        g_Wh + (size_t)n0 * EDIM, g_Wl + (size_t)n0 * EDIM, g_Wh + (size_t)n0 * EDIM };

    const bool av0 = (m0 + lr) < M;
    const bool av1 = (m0 + lr + 64) < M;

    float acc[4][4][4];
#pragma unroll
    for (int i = 0; i < 4; ++i)
#pragma unroll
        for (int j = 0; j < 4; ++j)
#pragma unroll
            for (int c = 0; c < 4; ++c) acc[i][j][c] = 0.f;

    const uint4 zed = make_uint4(0, 0, 0, 0);
    uint4 aR0, aR1, bR0, bR1;

    // prologue: it = 0 (seg 0, kc 0)
    {
        const __nv_bfloat16* aB = aSeg[0];
        const __nv_bfloat16* bB = bSeg[0];
        aR0 = av0 ? *reinterpret_cast<const uint4*>(aB + (size_t)lr * EDIM + lc) : zed;
        aR1 = av1 ? *reinterpret_cast<const uint4*>(aB + (size_t)(lr + 64) * EDIM + lc) : zed;
        bR0 = *reinterpret_cast<const uint4*>(bB + (size_t)lr * EDIM + lc);
        bR1 = *reinterpret_cast<const uint4*>(bB + (size_t)(lr + 64) * EDIM + lc);
    }

    for (int it = 0; it < NIT; ++it) {
        *reinterpret_cast<uint4*>(&As[lr][lc])      = aR0;
        *reinterpret_cast<uint4*>(&As[lr + 64][lc]) = aR1;
        *reinterpret_cast<uint4*>(&Bs[lr][lc])      = bR0;
        *reinterpret_cast<uint4*>(&Bs[lr + 64][lc]) = bR1;
        __syncthreads();

        if (it + 1 < NIT) {
            const int nit = it + 1;
            const int seg = nit >> 3;           // /NKC
            const int kc  = (nit & 7) * GBK;
            const __nv_bfloat16* aB = aSeg[seg];
            const __nv_bfloat16* bB = bSeg[seg];
            aR0 = av0 ? *reinterpret_cast<const uint4*>(aB + (size_t)lr * EDIM + kc + lc) : zed;
            aR1 = av1 ? *reinterpret_cast<const uint4*>(aB + (size_t)(lr + 64) * EDIM + kc + lc) : zed;
            bR0 = *reinterpret_cast<const uint4*>(bB + (size_t)lr * EDIM + kc + lc);
            bR1 = *reinterpret_cast<const uint4*>(bB + (size_t)(lr + 64) * EDIM + kc + lc);
        }

#pragma unroll
        for (int ks = 0; ks < 2; ++ks) {
            const int kk = ks * 16 + tig * 2;
            unsigned af[4][4], bf[4][2];
#pragma unroll
            for (int fi = 0; fi < 4; ++fi) {
                const int r = wm * 64 + fi * 16 + gid;
                af[fi][0] = *reinterpret_cast<const unsigned*>(&As[r][kk]);
                af[fi][1] = *reinterpret_cast<const unsigned*>(&As[r + 8][kk]);
                af[fi][2] = *reinterpret_cast<const unsigned*>(&As[r][kk + 8]);
                af[fi][3] = *reinterpret_cast<const unsigned*>(&As[r + 8][kk + 8]);
            }
#pragma unroll
            for (int fj = 0; fj < 4; ++fj) {
                const int r = wn * 32 + fj * 8 + gid;
                bf[fj][0] = *reinterpret_cast<const unsigned*>(&Bs[r][kk]);
                bf[fj][1] = *reinterpret_cast<const unsigned*>(&Bs[r][kk + 8]);
            }
#pragma unroll
            for (int fi = 0; fi < 4; ++fi)
#pragma unroll
                for (int fj = 0; fj < 4; ++fj)
                    mma16816(acc[fi][fj], af[fi], bf[fj]);
        }
        __syncthreads();
    }

    // Epilogue: bias + fp32 store (float2 per fragment row).
#pragma unroll
    for (int fj = 0; fj < 4; ++fj) {
        const int col = n0 + wn * 32 + fj * 8 + tig * 2;
        const float2 bv = *reinterpret_cast<const float2*>(&bias[col]);
#pragma unroll
        for (int fi = 0; fi < 4; ++fi) {
            const int r0 = m0 + wm * 64 + fi * 16 + gid;
            if (r0 < M)
                *reinterpret_cast<float2*>(&C[(size_t)r0 * EDIM + col]) =
                    make_float2(acc[fi][fj][0] + bv.x, acc[fi][fj][1] + bv.y);
            const int r1 = r0 + 8;
            if (r1 < M)
                *reinterpret_cast<float2*>(&C[(size_t)r1 * EDIM + col]) =
                    make_float2(acc[fi][fj][2] + bv.x, acc[fi][fj][3] + bv.y);
        }
    }
}

// ---------------------------------------------------------------------------
extern "C" void kernel_launch(void* const* d_in, const int* in_sizes, int n_in,
                              void* d_out, int out_size)
{
    const float* x     = (const float*)d_in[0];
    const float* theta = (const float*)d_in[1];
    const float* W     = (const float*)d_in[2];
    const float* bias  = (const float*)d_in[3];
    float* out = (float*)d_out;

    int ntok = in_sizes[0] / EDIM;
    if (ntok > MAXTOK) ntok = MAXTOK;

    wconv_kernel<<<EDIM * EDIM / (256 * 8), 256>>>(W);
    attn_kernel<<<(ntok + 3) / 4, 128>>>(x, theta, ntok);

    dim3 grid((ntok + GBM - 1) / GBM, EDIM / GBN);
    gemm_bf16s_kernel<<<grid, 256>>>(bias, out, ntok);
}